// round 17
// baseline (speedup 1.0000x reference)
#include <cuda_runtime.h>
#include <cuda_bf16.h>
#include <math.h>
#include <stdint.h>

#define NC 131071
#define NA 4095
#define NB 4095
#define TOTAL_NODES (NC + NA + NB)
#define HDIM 128
#define VOCAB 50000
#define VT 391

__device__ float g_h[(size_t)TOTAL_NODES * HDIM];
__device__ float g_c[(size_t)TOTAL_NODES * HDIM];
__device__ float g_T[(size_t)VOCAB * 512];
__device__ uint32_t g_Ah[(size_t)VT * 128 * 64];
__device__ uint32_t g_Al[(size_t)VT * 128 * 64];
__device__ uint32_t g_Bh[512 * 64];
__device__ uint32_t g_Bl[512 * 64];
__device__ uint32_t g_UH[512 * 64];
__device__ uint32_t g_UL[512 * 64];
__device__ float g_Ut[512 * 128];                   // fp32 [n][k] transposed [U_iou|U_f]
// scratch (per-segment offsets: cube 0 / a 32768 / b 33792 for Y1; 0 / 65536 / 67584 for Y2)
__device__ float g_Y1[(size_t)34816 * 384];
__device__ float g_Y2[(size_t)69632 * 128];

struct MSeg { int gq0, tEnd, y1o, y2o; };
struct GSeg { const int* feats; int gp0, gq0, y1o, y2o, bEnd; };
struct SSeg { const int* feats; int gp0, gq0, bEnd; };

__device__ __forceinline__ float sigf(float x) { return 1.0f / (1.0f + expf(-x)); }

__device__ __forceinline__ void mma16(float* c, const uint32_t* a, const uint32_t* b) {
    asm volatile(
        "mma.sync.aligned.m16n8k16.row.col.f32.bf16.bf16.f32 "
        "{%0,%1,%2,%3}, {%4,%5,%6,%7}, {%8,%9}, {%0,%1,%2,%3};"
        : "+f"(c[0]), "+f"(c[1]), "+f"(c[2]), "+f"(c[3])
        : "r"(a[0]), "r"(a[1]), "r"(a[2]), "r"(a[3]), "r"(b[0]), "r"(b[1]));
}

__device__ __forceinline__ void split2(float x, float y, uint32_t& hp, uint32_t& lp) {
    __nv_bfloat162 h = __floats2bfloat162_rn(x, y);
    hp = *(uint32_t*)&h;
    float lx = x - __bfloat162float(h.x);
    float ly = y - __bfloat162float(h.y);
    __nv_bfloat162 l = __floats2bfloat162_rn(lx, ly);
    lp = *(uint32_t*)&l;
}

// ---------------------------------------------------------------------------
// Prep kernels — destination globals written BY NAME in device code only.
// ---------------------------------------------------------------------------
__global__ void __launch_bounds__(256)
prepA_kernel(const float* __restrict__ emb)
{
    int idx = blockIdx.x * 256 + threadIdx.x;
    int v = idx >> 6, p = idx & 63;
    float x0 = 0.f, x1 = 0.f;
    if (v < VOCAB) {
        x0 = __ldg(&emb[(size_t)v * 128 + 2 * p]);
        x1 = __ldg(&emb[(size_t)v * 128 + 2 * p + 1]);
    }
    uint32_t hp, lp; split2(x0, x1, hp, lp);
    g_Ah[idx] = hp;
    g_Al[idx] = lp;
}

__global__ void __launch_bounds__(256)
prepW_kernel(const float* __restrict__ M1, const float* __restrict__ M2)
{
    int idx = blockIdx.x * 256 + threadIdx.x;
    int n = idx >> 6, p = idx & 63;
    int k0 = 2 * p;
    float x0, x1;
    if (n < 384) {
        x0 = __ldg(&M1[(size_t)k0 * 384 + n]);
        x1 = __ldg(&M1[(size_t)(k0 + 1) * 384 + n]);
    } else {
        x0 = __ldg(&M2[(size_t)k0 * 128 + (n - 384)]);
        x1 = __ldg(&M2[(size_t)(k0 + 1) * 128 + (n - 384)]);
    }
    uint32_t hp, lp; split2(x0, x1, hp, lp);
    g_Bh[idx] = hp;
    g_Bl[idx] = lp;
}

__global__ void __launch_bounds__(256)
prepU_kernel(const float* __restrict__ M1, const float* __restrict__ M2)
{
    int idx = blockIdx.x * 256 + threadIdx.x;
    int n = idx >> 6, p = idx & 63;
    int k0 = 2 * p;
    float x0, x1;
    if (n < 384) {
        x0 = __ldg(&M1[(size_t)k0 * 384 + n]);
        x1 = __ldg(&M1[(size_t)(k0 + 1) * 384 + n]);
    } else {
        x0 = __ldg(&M2[(size_t)k0 * 128 + (n - 384)]);
        x1 = __ldg(&M2[(size_t)(k0 + 1) * 128 + (n - 384)]);
    }
    uint32_t hp, lp; split2(x0, x1, hp, lp);
    g_UH[idx] = hp;
    g_UL[idx] = lp;
    g_Ut[(size_t)n * 128 + k0]     = x0;
    g_Ut[(size_t)n * 128 + k0 + 1] = x1;
}

// ---------------------------------------------------------------------------
// Table GEMM (proven, verbatim)
// ---------------------------------------------------------------------------
extern __shared__ uint32_t sh[];
__global__ void __launch_bounds__(256)
table_mma(const float* __restrict__ biou, const float* __restrict__ bf)
{
    const int tid = threadIdx.x, w = tid >> 5, lane = tid & 31;
    const int g = lane >> 2, tg = lane & 3;
    const int nBlk = blockIdx.y * 64;

    uint32_t* Ah = sh;
    uint32_t* Al = sh + 8704;
    uint32_t* Bh = sh + 17408;
    uint32_t* Bl = sh + 21760;

    const uint4* srcAh = (const uint4*)(g_Ah + (size_t)blockIdx.x * 8192);
    const uint4* srcAl = (const uint4*)(g_Al + (size_t)blockIdx.x * 8192);
    for (int i = tid; i < 2048; i += 256) {
        int r = i >> 4, q = i & 15;
        *(uint4*)(Ah + r * 68 + q * 4) = srcAh[i];
        *(uint4*)(Al + r * 68 + q * 4) = srcAl[i];
    }
    for (int i = tid; i < 1024; i += 256) {
        int n = i >> 4, q = i & 15;
        *(uint4*)(Bh + n * 68 + q * 4) = *(const uint4*)(g_Bh + (size_t)(nBlk + n) * 64 + q * 4);
        *(uint4*)(Bl + n * 68 + q * 4) = *(const uint4*)(g_Bl + (size_t)(nBlk + n) * 64 + q * 4);
    }
    __syncthreads();

    const int wm = (w & 3) * 32;
    const int wn = (w >> 2) * 32;

    float acc[2][4][4];
    #pragma unroll
    for (int mt = 0; mt < 2; mt++)
        #pragma unroll
        for (int nt = 0; nt < 4; nt++)
            #pragma unroll
            for (int e = 0; e < 4; e++) acc[mt][nt][e] = 0.f;

    #pragma unroll
    for (int ks = 0; ks < 8; ks++) {
        const int p0 = ks * 8;
        uint32_t ah[2][4], al[2][4], bh[4][2], bl[4][2];
        #pragma unroll
        for (int mt = 0; mt < 2; mt++) {
            int r0 = wm + mt * 16 + g;
            ah[mt][0] = Ah[r0 * 68 + p0 + tg];
            ah[mt][1] = Ah[(r0 + 8) * 68 + p0 + tg];
            ah[mt][2] = Ah[r0 * 68 + p0 + tg + 4];
            ah[mt][3] = Ah[(r0 + 8) * 68 + p0 + tg + 4];
            al[mt][0] = Al[r0 * 68 + p0 + tg];
            al[mt][1] = Al[(r0 + 8) * 68 + p0 + tg];
            al[mt][2] = Al[r0 * 68 + p0 + tg + 4];
            al[mt][3] = Al[(r0 + 8) * 68 + p0 + tg + 4];
        }
        #pragma unroll
        for (int nt = 0; nt < 4; nt++) {
            int col = wn + nt * 8 + g;
            bh[nt][0] = Bh[col * 68 + p0 + tg];
            bh[nt][1] = Bh[col * 68 + p0 + tg + 4];
            bl[nt][0] = Bl[col * 68 + p0 + tg];
            bl[nt][1] = Bl[col * 68 + p0 + tg + 4];
        }
        #pragma unroll
        for (int mt = 0; mt < 2; mt++)
            #pragma unroll
            for (int nt = 0; nt < 4; nt++) {
                mma16(acc[mt][nt], ah[mt], bh[nt]);
                mma16(acc[mt][nt], al[mt], bh[nt]);
                mma16(acc[mt][nt], ah[mt], bl[nt]);
            }
    }

    #pragma unroll
    for (int mt = 0; mt < 2; mt++) {
        #pragma unroll
        for (int nt = 0; nt < 4; nt++) {
            int colg = nBlk + wn + nt * 8 + tg * 2;
            float bias0 = (colg < 384) ? __ldg(&biou[colg]) : __ldg(&bf[colg - 384]);
            float bias1 = (colg + 1 < 384) ? __ldg(&biou[colg + 1]) : __ldg(&bf[colg + 1 - 384]);
            int r0 = blockIdx.x * 128 + wm + mt * 16 + g;
            if (r0 < VOCAB) {
                g_T[(size_t)r0 * 512 + colg]     = acc[mt][nt][0] + bias0;
                g_T[(size_t)r0 * 512 + colg + 1] = acc[mt][nt][1] + bias1;
            }
            if (r0 + 8 < VOCAB) {
                g_T[(size_t)(r0 + 8) * 512 + colg]     = acc[mt][nt][2] + bias0;
                g_T[(size_t)(r0 + 8) * 512 + colg + 1] = acc[mt][nt][3] + bias1;
            }
        }
    }
}

// ---------------------------------------------------------------------------
// Fused K1+K2, 3-segment dispatch. grid = (tEnd2, 10).
// y<6: Y1 chunk y for 128 parents. y>=6: Y2 job xl*4+(y-6).
// Partial segments (M=64): extra rows read/written are in-bounds garbage,
// never consumed by gate.
// ---------------------------------------------------------------------------
__global__ void __launch_bounds__(256)
mmaLevel_kernel(MSeg m0, MSeg m1, MSeg m2)
{
    const int tid = threadIdx.x, w = tid >> 5, lane = tid & 31;
    const int g = lane >> 2, tg = lane & 3;

    int x = blockIdx.x;
    int gq0, xl, y1o, y2o;
    if (x < m0.tEnd)      { gq0 = m0.gq0; xl = x;           y1o = m0.y1o; y2o = m0.y2o; }
    else if (x < m1.tEnd) { gq0 = m1.gq0; xl = x - m0.tEnd; y1o = m1.y1o; y2o = m1.y2o; }
    else                  { gq0 = m2.gq0; xl = x - m1.tEnd; y1o = m2.y1o; y2o = m2.y2o; }

    uint32_t* Ah = sh;
    uint32_t* Al = sh + 8704;
    uint32_t* Bh = sh + 17408;
    uint32_t* Bl = sh + 21760;

    if (blockIdx.y < 6) {
        const int nBlk = blockIdx.y * 64;
        const int rowBase = gq0 + xl * 256;
        for (int i = tid; i < 8192; i += 256) {
            int r = i >> 6, p = i & 63;
            float2 a = ((const float2*)(g_h + (size_t)(rowBase + 2 * r) * 128))[p];
            float2 b = ((const float2*)(g_h + (size_t)(rowBase + 2 * r + 1) * 128))[p];
            uint32_t hp, lp; split2(a.x + b.x, a.y + b.y, hp, lp);
            Ah[r * 68 + p] = hp;
            Al[r * 68 + p] = lp;
        }
        for (int i = tid; i < 1024; i += 256) {
            int n = i >> 4, q = i & 15;
            *(uint4*)(Bh + n * 68 + q * 4) = *(const uint4*)(g_UH + (size_t)(nBlk + n) * 64 + q * 4);
            *(uint4*)(Bl + n * 68 + q * 4) = *(const uint4*)(g_UL + (size_t)(nBlk + n) * 64 + q * 4);
        }
        __syncthreads();

        const int wm = (w & 3) * 32;
        const int wn = (w >> 2) * 32;

        float acc[2][4][4];
        #pragma unroll
        for (int mt = 0; mt < 2; mt++)
            #pragma unroll
            for (int nt = 0; nt < 4; nt++)
                #pragma unroll
                for (int e = 0; e < 4; e++) acc[mt][nt][e] = 0.f;

        #pragma unroll
        for (int ks = 0; ks < 8; ks++) {
            const int p0 = ks * 8;
            uint32_t ah[2][4], al[2][4], bh[4][2], bl[4][2];
            #pragma unroll
            for (int mt = 0; mt < 2; mt++) {
                int r0 = wm + mt * 16 + g;
                ah[mt][0] = Ah[r0 * 68 + p0 + tg];
                ah[mt][1] = Ah[(r0 + 8) * 68 + p0 + tg];
                ah[mt][2] = Ah[r0 * 68 + p0 + tg + 4];
                ah[mt][3] = Ah[(r0 + 8) * 68 + p0 + tg + 4];
                al[mt][0] = Al[r0 * 68 + p0 + tg];
                al[mt][1] = Al[(r0 + 8) * 68 + p0 + tg];
                al[mt][2] = Al[r0 * 68 + p0 + tg + 4];
                al[mt][3] = Al[(r0 + 8) * 68 + p0 + tg + 4];
            }
            #pragma unroll
            for (int nt = 0; nt < 4; nt++) {
                int col = wn + nt * 8 + g;
                bh[nt][0] = Bh[col * 68 + p0 + tg];
                bh[nt][1] = Bh[col * 68 + p0 + tg + 4];
                bl[nt][0] = Bl[col * 68 + p0 + tg];
                bl[nt][1] = Bl[col * 68 + p0 + tg + 4];
            }
            #pragma unroll
            for (int mt = 0; mt < 2; mt++)
                #pragma unroll
                for (int nt = 0; nt < 4; nt++) {
                    mma16(acc[mt][nt], ah[mt], bh[nt]);
                    mma16(acc[mt][nt], al[mt], bh[nt]);
                    mma16(acc[mt][nt], ah[mt], bl[nt]);
                }
        }

        #pragma unroll
        for (int mt = 0; mt < 2; mt++) {
            #pragma unroll
            for (int nt = 0; nt < 4; nt++) {
                int colg = nBlk + wn + nt * 8 + tg * 2;
                int r0 = y1o + xl * 128 + wm + mt * 16 + g;
                g_Y1[(size_t)r0 * 384 + colg]           = acc[mt][nt][0];
                g_Y1[(size_t)r0 * 384 + colg + 1]       = acc[mt][nt][1];
                g_Y1[(size_t)(r0 + 8) * 384 + colg]     = acc[mt][nt][2];
                g_Y1[(size_t)(r0 + 8) * 384 + colg + 1] = acc[mt][nt][3];
            }
        }
    } else {
        const int job = xl * 4 + (blockIdx.y - 6);
        const int xx = job >> 1;
        const int nb = job & 1;
        const int rowBase = gq0 + xx * 128;
        for (int i = tid; i < 8192; i += 256) {
            int r = i >> 6, p = i & 63;
            float2 a = ((const float2*)(g_h + (size_t)(rowBase + r) * 128))[p];
            uint32_t hp, lp; split2(a.x, a.y, hp, lp);
            Ah[r * 68 + p] = hp;
            Al[r * 68 + p] = lp;
        }
        const int bBase = 384 + nb * 64;
        for (int i = tid; i < 1024; i += 256) {
            int n = i >> 4, q = i & 15;
            *(uint4*)(Bh + n * 68 + q * 4) = *(const uint4*)(g_UH + (size_t)(bBase + n) * 64 + q * 4);
            *(uint4*)(Bl + n * 68 + q * 4) = *(const uint4*)(g_UL + (size_t)(bBase + n) * 64 + q * 4);
        }
        __syncthreads();

        const int wm = (w & 3) * 32;
        const int wn = (w >> 2) * 32;

        float acc[2][4][4];
        #pragma unroll
        for (int mt = 0; mt < 2; mt++)
            #pragma unroll
            for (int nt = 0; nt < 4; nt++)
                #pragma unroll
                for (int e = 0; e < 4; e++) acc[mt][nt][e] = 0.f;

        #pragma unroll
        for (int ks = 0; ks < 8; ks++) {
            const int p0 = ks * 8;
            uint32_t ah[2][4], al[2][4], bh[4][2], bl[4][2];
            #pragma unroll
            for (int mt = 0; mt < 2; mt++) {
                int r0 = wm + mt * 16 + g;
                ah[mt][0] = Ah[r0 * 68 + p0 + tg];
                ah[mt][1] = Ah[(r0 + 8) * 68 + p0 + tg];
                ah[mt][2] = Ah[r0 * 68 + p0 + tg + 4];
                ah[mt][3] = Ah[(r0 + 8) * 68 + p0 + tg + 4];
                al[mt][0] = Al[r0 * 68 + p0 + tg];
                al[mt][1] = Al[(r0 + 8) * 68 + p0 + tg];
                al[mt][2] = Al[r0 * 68 + p0 + tg + 4];
                al[mt][3] = Al[(r0 + 8) * 68 + p0 + tg + 4];
            }
            #pragma unroll
            for (int nt = 0; nt < 4; nt++) {
                int col = wn + nt * 8 + g;
                bh[nt][0] = Bh[col * 68 + p0 + tg];
                bh[nt][1] = Bh[col * 68 + p0 + tg + 4];
                bl[nt][0] = Bl[col * 68 + p0 + tg];
                bl[nt][1] = Bl[col * 68 + p0 + tg + 4];
            }
            #pragma unroll
            for (int mt = 0; mt < 2; mt++)
                #pragma unroll
                for (int nt = 0; nt < 4; nt++) {
                    mma16(acc[mt][nt], ah[mt], bh[nt]);
                    mma16(acc[mt][nt], al[mt], bh[nt]);
                    mma16(acc[mt][nt], ah[mt], bl[nt]);
                }
        }

        #pragma unroll
        for (int mt = 0; mt < 2; mt++) {
            #pragma unroll
            for (int nt = 0; nt < 4; nt++) {
                int colg = nb * 64 + wn + nt * 8 + tg * 2;
                int r0 = y2o + xx * 128 + wm + mt * 16 + g;
                g_Y2[(size_t)r0 * 128 + colg]           = acc[mt][nt][0];
                g_Y2[(size_t)r0 * 128 + colg + 1]       = acc[mt][nt][1];
                g_Y2[(size_t)(r0 + 8) * 128 + colg]     = acc[mt][nt][2];
                g_Y2[(size_t)(r0 + 8) * 128 + colg + 1] = acc[mt][nt][3];
            }
        }
    }
}

// ---------------------------------------------------------------------------
// Gate kernel, 3-segment dispatch. 2 parents per block.
// ---------------------------------------------------------------------------
__global__ void __launch_bounds__(256)
gate_kernel(GSeg s0, GSeg s1, GSeg s2)
{
    int bid = blockIdx.x;
    GSeg s; int rel;
    if (bid < s0.bEnd)      { s = s0; rel = bid; }
    else if (bid < s1.bEnd) { s = s1; rel = bid - s0.bEnd; }
    else                    { s = s2; rel = bid - s1.bEnd; }

    int j = rel * 2 + (threadIdx.x >> 7);
    int col = threadIdx.x & 127;
    int gp = s.gp0 + j;
    int f = __ldg(&s.feats[j]);
    const float* Tf  = g_T + (size_t)f * 512;
    const float* Y1r = g_Y1 + (size_t)(s.y1o + j) * 384;
    float iv = sigf(__ldg(&Y1r[col])        + __ldg(&Tf[col]));
    float ov = sigf(__ldg(&Y1r[128 + col])  + __ldg(&Tf[128 + col]));
    float uv = tanhf(__ldg(&Y1r[256 + col]) + __ldg(&Tf[256 + col]));
    float xf = __ldg(&Tf[384 + col]);
    float f0 = sigf(xf + __ldg(&g_Y2[(size_t)(s.y2o + 2 * j) * 128 + col]));
    float f1 = sigf(xf + __ldg(&g_Y2[(size_t)(s.y2o + 2 * j + 1) * 128 + col]));
    float c0 = __ldg(&g_c[(size_t)(s.gq0 + 2 * j) * 128 + col]);
    float c1 = __ldg(&g_c[(size_t)(s.gq0 + 2 * j + 1) * 128 + col]);
    float cc = iv * uv + f0 * c0 + f1 * c1;
    g_c[(size_t)gp * 128 + col] = cc;
    g_h[(size_t)gp * 128 + col] = ov * tanhf(cc);
}

// ---------------------------------------------------------------------------
// Small-level kernel: ONE parent per block; 640 length-128 dot products
// spread over 256 threads against fp32 transposed U (g_Ut), then gates.
// ---------------------------------------------------------------------------
__global__ void __launch_bounds__(256)
small_level(SSeg s0, SSeg s1, SSeg s2)
{
    __shared__ float hx[384];    // h0 | h1 | hs
    __shared__ float acc[640];
    __shared__ int sF;

    int bid = blockIdx.x;
    SSeg s; int j;
    if (bid < s0.bEnd)      { s = s0; j = bid; }
    else if (bid < s1.bEnd) { s = s1; j = bid - s0.bEnd; }
    else                    { s = s2; j = bid - s1.bEnd; }

    const int tid = threadIdx.x;
    if (tid < 128)      hx[tid]       = g_h[(size_t)(s.gq0 + 2 * j) * 128 + tid];
    else                hx[tid]       = g_h[(size_t)(s.gq0 + 2 * j + 1) * 128 + (tid - 128)];
    if (tid == 0) sF = __ldg(&s.feats[j]);
    __syncthreads();
    if (tid < 128) hx[256 + tid] = hx[tid] + hx[128 + tid];
    __syncthreads();

    for (int o = tid; o < 640; o += 256) {
        const float* x = (o < 384) ? (hx + 256) : ((o < 512) ? hx : (hx + 128));
        int n = (o < 512) ? o : (o - 128);
        const float* u = g_Ut + (size_t)n * 128;
        float sum = 0.f;
        #pragma unroll 8
        for (int k = 0; k < 128; k++) sum = fmaf(x[k], __ldg(&u[k]), sum);
        acc[o] = sum;
    }
    __syncthreads();

    if (tid < 128) {
        int col = tid;
        const float* Tf = g_T + (size_t)sF * 512;
        float iv = sigf(acc[col]        + __ldg(&Tf[col]));
        float ov = sigf(acc[128 + col]  + __ldg(&Tf[128 + col]));
        float uv = tanhf(acc[256 + col] + __ldg(&Tf[256 + col]));
        float xf = __ldg(&Tf[384 + col]);
        float f0 = sigf(xf + acc[384 + col]);
        float f1 = sigf(xf + acc[512 + col]);
        float c0 = g_c[(size_t)(s.gq0 + 2 * j) * 128 + col];
        float c1 = g_c[(size_t)(s.gq0 + 2 * j + 1) * 128 + col];
        float cc = iv * uv + f0 * c0 + f1 * c1;
        g_c[(size_t)(s.gp0 + j) * 128 + col] = cc;
        g_h[(size_t)(s.gp0 + j) * 128 + col] = ov * tanhf(cc);
    }
}

// ---------------------------------------------------------------------------
// Leaf kernel (proven, verbatim)
// ---------------------------------------------------------------------------
#define LEAVES_C 65536
#define LEAVES_AB 2048
__global__ void __launch_bounds__(256)
leaf_kernel(const int* __restrict__ cf, const int* __restrict__ af,
            const int* __restrict__ bfeat)
{
    int node = blockIdx.x * 2 + (threadIdx.x >> 7);
    int col = threadIdx.x & 127;
    int grow; const int* fp; int loc;
    if (node < LEAVES_C)                  { loc = node;                        grow = loc;           fp = cf; }
    else if (node < LEAVES_C + LEAVES_AB) { loc = node - LEAVES_C;             grow = NC + loc;      fp = af; }
    else                                  { loc = node - LEAVES_C - LEAVES_AB; grow = NC + NA + loc; fp = bfeat; }
    int f = __ldg(&fp[loc]);
    const float* T = g_T + (size_t)f * 512;
    float iv = sigf(__ldg(&T[col]));
    float ov = sigf(__ldg(&T[128 + col]));
    float uv = tanhf(__ldg(&T[256 + col]));
    float c = iv * uv;
    g_c[(size_t)grow * HDIM + col] = c;
    g_h[(size_t)grow * HDIM + col] = ov * tanhf(c);
}

// ---------------------------------------------------------------------------
// Fusion head
// ---------------------------------------------------------------------------
__global__ void final_kernel(const float* __restrict__ fc1w, const float* __restrict__ fc1b,
                             const float* __restrict__ fc2w, const float* __restrict__ fc2b,
                             float* __restrict__ out)
{
    __shared__ float red[128]; __shared__ float hv[128]; __shared__ float y1[64];
    int t = threadIdx.x;
    const float* hC = g_h + (size_t)(NC - 1) * HDIM;
    const float* hA = g_h + (size_t)(NC + NA - 1) * HDIM;
    const float* hB = g_h + (size_t)(NC + NA + NB - 1) * HDIM;
    red[t] = hB[t] * hC[t];
    __syncthreads();
    for (int ss = 64; ss > 0; ss >>= 1) { if (t < ss) red[t] += red[t + ss]; __syncthreads(); }
    hv[t] = hA[t] * red[0];
    __syncthreads();
    if (t < 64) {
        float a = fc1b[t];
        #pragma unroll 4
        for (int i = 0; i < 128; i++) a = fmaf(hv[i], fc1w[i * 64 + t], a);
        y1[t] = fmaxf(a, 0.f);
    }
    __syncthreads();
    if (t < 3) {
        float a = fc2b[t];
        #pragma unroll
        for (int i = 0; i < 64; i++) a = fmaf(y1[i], fc2w[i * 3 + t], a);
        out[t] = fmaxf(a, 0.f);
    }
}

// ---------------------------------------------------------------------------
// Host side
// ---------------------------------------------------------------------------
struct LevelInfo { int pLoc, qLoc, M; };
static inline LevelInfo level_info(int D, int it)
{
    int N = (1 << D) - 1;
    int d = D - 1 - it;
    LevelInfo L;
    L.M = 1 << d;
    L.pLoc = N - (1 << (d + 1)) + 1;
    L.qLoc = N - (1 << (d + 2)) + 1;
    return L;
}

extern "C" void kernel_launch(void* const* d_in, const int* in_sizes, int n_in,
                              void* d_out, int out_size)
{
    const int*   cf    = (const int*)  d_in[0];
    const int*   af    = (const int*)  d_in[4];
    const int*   bfeat = (const int*)  d_in[8];
    const float* emb   = (const float*)d_in[12];
    const float* W_iou = (const float*)d_in[13];
    const float* b_iou = (const float*)d_in[14];
    const float* U_iou = (const float*)d_in[15];
    const float* W_f   = (const float*)d_in[16];
    const float* b_f   = (const float*)d_in[17];
    const float* U_f   = (const float*)d_in[18];
    const float* fc1w  = (const float*)d_in[19];
    const float* fc1b  = (const float*)d_in[20];
    const float* fc2w  = (const float*)d_in[21];
    const float* fc2b  = (const float*)d_in[22];

    const int SM_AB = 104448;
    cudaFuncSetAttribute(table_mma,       cudaFuncAttributeMaxDynamicSharedMemorySize, SM_AB);
    cudaFuncSetAttribute(mmaLevel_kernel, cudaFuncAttributeMaxDynamicSharedMemorySize, SM_AB);

    prepA_kernel<<<VT * 32, 256>>>(emb);
    prepW_kernel<<<128, 256>>>(W_iou, W_f);
    prepU_kernel<<<128, 256>>>(U_iou, U_f);
    {
        dim3 grid(VT, 8);
        table_mma<<<grid, 256, SM_AB>>>(b_iou, b_f);
    }
    leaf_kernel<<<(LEAVES_C + 2 * LEAVES_AB) / 2, 256>>>(cf, af, bfeat);

    const int baseC = 0, baseA = NC, baseB = NC + NA;
    // Y1 offsets: cube 0, a 32768, b 33792. Y2 offsets: cube 0, a 65536, b 67584.
    for (int it = 1; it <= 8; it++) {
        LevelInfo Lc = level_info(17, it);
        int tilesC = Lc.M / 128;
        bool ab = (it <= 5);
        LevelInfo La = ab ? level_info(12, it) : LevelInfo{0, 0, 0};
        int tilesA = ab ? ((La.M + 127) / 128) : 0;

        MSeg m0 = { baseC + Lc.qLoc, tilesC,                0,     0     };
        MSeg m1 = { baseA + La.qLoc, tilesC + tilesA,       32768, 65536 };
        MSeg m2 = { baseB + La.qLoc, tilesC + 2 * tilesA,   33792, 67584 };
        dim3 gg(tilesC + 2 * tilesA, 10);
        mmaLevel_kernel<<<gg, 256, SM_AB>>>(m0, m1, m2);

        int e0 = Lc.M / 2;
        int e1 = e0 + (ab ? La.M / 2 : 0);
        int e2 = e1 + (ab ? La.M / 2 : 0);
        GSeg g0 = { cf + Lc.pLoc,    baseC + Lc.pLoc, baseC + Lc.qLoc, 0,     0,     e0 };
        GSeg g1 = { ab ? af + La.pLoc : cf,    baseA + La.pLoc, baseA + La.qLoc, 32768, 65536, e1 };
        GSeg g2 = { ab ? bfeat + La.pLoc : cf, baseB + La.pLoc, baseB + La.qLoc, 33792, 67584, e2 };
        gate_kernel<<<e2, 256>>>(g0, g1, g2);
    }

    // tail: cube it=9..16 (small), a/b it=6..11 (small)
    for (int it = 6; it <= 16; it++) {
        bool hasC = (it >= 9);
        bool hasAB = (it <= 11);
        LevelInfo Lc = hasC ? level_info(17, it) : LevelInfo{0, 0, 0};
        LevelInfo La = hasAB ? level_info(12, it) : LevelInfo{0, 0, 0};
        int e0 = hasC ? Lc.M : 0;
        int e1 = e0 + (hasAB ? La.M : 0);
        int e2 = e1 + (hasAB ? La.M : 0);
        SSeg s0 = { hasC ? cf + Lc.pLoc : cf,       baseC + Lc.pLoc, baseC + Lc.qLoc, e0 };
        SSeg s1 = { hasAB ? af + La.pLoc : cf,      baseA + La.pLoc, baseA + La.qLoc, e1 };
        SSeg s2 = { hasAB ? bfeat + La.pLoc : cf,   baseB + La.pLoc, baseB + La.qLoc, e2 };
        if (e2 > 0) small_level<<<e2, 256>>>(s0, s1, s2);
    }

    final_kernel<<<1, 128>>>(fc1w, fc1b, fc2w, fc2b, (float*)d_out);
}